// round 15
// baseline (speedup 1.0000x reference)
#include <cuda_runtime.h>
#include <cuda_bf16.h>
#include <cstdint>

#define KK 512
#define DD 64
#define HWSZ 4096
#define CCH 64
#define NFLAT 131072
#define NTILES 1024            // NFLAT / 128
#define NCTA 148
#define TPB 512

#define LOSS_OFF   0ULL
#define QOUT_OFF   1ULL
#define PERP_OFF   8388609ULL
#define ENC_OFF    8388610ULL   // elem offset == 2 (mod 4)
#define QFLAT_OFF  75497474ULL  // elem offset == 2 (mod 4)

#define TAU_GAP  6e-4f
#define TAU_BAND 2.4e-3f

// ---- dynamic smem byte offsets ----
#define SM_HIST  0              // 512 int
#define SM_SSE   2048           // double
#define SM_FLAG  2056           // unsigned
#define SM_HN    2176           // 512 float (reused as finalize scratch)
#define SM_BIDX  4224           // 2 x 128 int (double-buffered)
#define SM_X0    5376           // 128 x 66 fp32 = 33792 B
#define SM_X1    39168
#define SM_BHI   72960          // 512 x 144B bf16
#define SM_BLO   146688
#define SM_TOTAL 220416

#define XSTR 66
#define BSTR 144

__device__ int      g_hist_part[NCTA][KK];
__device__ double   g_sse_part[NCTA];
__device__ unsigned g_done;

__device__ __forceinline__ uint32_t smem_u32(const void* p) {
    uint32_t a;
    asm("{ .reg .u64 t; cvta.to.shared.u64 t, %1; cvt.u32.u64 %0, t; }" : "=r"(a) : "l"(p));
    return a;
}
__device__ __forceinline__ void ldsm_x4_nv(uint32_t* r, uint32_t addr) {
    asm("ldmatrix.sync.aligned.m8n8.x4.shared.b16 {%0,%1,%2,%3}, [%4];"
        : "=r"(r[0]), "=r"(r[1]), "=r"(r[2]), "=r"(r[3]) : "r"(addr));
}
__device__ __forceinline__ void mma_bf16(float& c0, float& c1, float& c2, float& c3,
                                         uint32_t a0, uint32_t a1, uint32_t a2, uint32_t a3,
                                         uint32_t b0, uint32_t b1) {
    asm("mma.sync.aligned.m16n8k16.row.col.f32.bf16.bf16.f32 "
        "{%0,%1,%2,%3}, {%4,%5,%6,%7}, {%8,%9}, {%0,%1,%2,%3};"
        : "+f"(c0), "+f"(c1), "+f"(c2), "+f"(c3)
        : "r"(a0), "r"(a1), "r"(a2), "r"(a3), "r"(b0), "r"(b1));
}
__device__ __forceinline__ void cp_async4(uint32_t dst, const void* src) {
    asm volatile("cp.async.ca.shared.global [%0], [%1], 4;" :: "r"(dst), "l"(src));
}
__device__ __forceinline__ void cp_wait_all() {
    asm volatile("cp.async.wait_all;" ::: "memory");
}
__device__ __forceinline__ void split_pair(float f0, float f1, uint32_t& hi, uint32_t& lo) {
    __nv_bfloat16 h0 = __float2bfloat16_rn(f0), h1 = __float2bfloat16_rn(f1);
    hi = ((uint32_t)__bfloat16_as_ushort(h1) << 16) | (uint32_t)__bfloat16_as_ushort(h0);
    float r0 = f0 - __bfloat162float(h0), r1 = f1 - __bfloat162float(h1);
    __nv_bfloat16 l0 = __float2bfloat16_rn(r0), l1 = __float2bfloat16_rn(r1);
    lo = ((uint32_t)__bfloat16_as_ushort(l1) << 16) | (uint32_t)__bfloat16_as_ushort(l0);
}
#define UPD(b, b2, i, s, n) { bool p_ = (s) > (b); \
    (b2) = p_ ? (b) : fmaxf((b2), (s)); (i) = p_ ? (n) : (i); (b) = p_ ? (s) : (b); }

// ================= single fused kernel (warp-specialized) =================
__global__ __launch_bounds__(TPB, 1)
void vq_mma_kernel(const float* __restrict__ in,
                   const float* __restrict__ emb,
                   float* __restrict__ out)
{
    extern __shared__ __align__(128) char smem[];
    const uint32_t sb = smem_u32(smem);
    const int tid  = threadIdx.x;
    const int cta  = blockIdx.x;
    const int lane = tid & 31;
    const int w    = tid >> 5;

    int*    shist = (int*)(smem + SM_HIST);
    float*  shn   = (float*)(smem + SM_HN);
    int*    sBidx = (int*)(smem + SM_BIDX);
    float*  sXb[2] = { (float*)(smem + SM_X0), (float*)(smem + SM_X1) };

    for (int i = tid; i < KK; i += TPB) shist[i] = 0;
    if (tid == 0) *(double*)(smem + SM_SSE) = 0.0;

    // ---- codebook -> SMEM bf16 hi/lo (once; immutable) + half-norms ----
    for (int i = tid; i < KK * 16; i += TPB) {
        float4 v = __ldg((const float4*)emb + i);
        int r = i >> 4, c4 = i & 15;
        uint32_t h0, l0, h1, l1;
        split_pair(v.x, v.y, h0, l0);
        split_pair(v.z, v.w, h1, l1);
        *(uint2*)(smem + SM_BHI + r * BSTR + c4 * 8) = make_uint2(h0, h1);
        *(uint2*)(smem + SM_BLO + r * BSTR + c4 * 8) = make_uint2(l0, l1);
    }
    for (int r = tid; r < KK; r += TPB) {
        const float4* e4 = (const float4*)(emb + (size_t)r * DD);
        float acc = 0.f;
        #pragma unroll
        for (int j = 0; j < 16; j++) {
            float4 q = __ldg(e4 + j);
            acc = fmaf(q.x, q.x, acc); acc = fmaf(q.y, q.y, acc);
            acc = fmaf(q.z, q.z, acc); acc = fmaf(q.w, q.w, acc);
        }
        shn[r] = 0.5f * acc;
    }

    // ---- prologue: first X tile into buf 0 (all threads) ----
    {
        const int n0g = cta << 7;
        const float* base = in + (size_t)(n0g >> 12) * CCH * HWSZ + (n0g & 4095);
        float* sX = sXb[0];
        for (int i = tid; i < 128 * DD; i += TPB) {
            int d = i >> 7, r = i & 127;
            sX[r * XSTR + d] = __ldg(base + (size_t)d * HWSZ + r);
        }
    }
    __syncthreads();

    int p = 0, it = 0;
    for (int tile = cta; tile < NTILES; tile += NCTA, p ^= 1, it++) {
        const int n0g = tile << 7;
        float* sX = sXb[p];

        if (w < 8) {
            // ================= SCAN warps =================
            const int grp  = lane >> 2;
            const int tig  = lane & 3;
            const int rowA = w * 16 + grp;
            const int rowB = rowA + 8;
            const uint32_t bofs = (uint32_t)((lane & 7) + ((lane >> 4) & 1) * 8) * BSTR
                                + (uint32_t)((lane >> 3) & 1) * 16;

            // build A fragments (hi/lo) from sX
            uint32_t ah[4][4], al[4][4];
            #pragma unroll
            for (int kb = 0; kb < 4; kb++) {
                int k = kb * 16 + tig * 2;
                float2 p00 = *(const float2*)(sX + rowA * XSTR + k);
                float2 p10 = *(const float2*)(sX + rowB * XSTR + k);
                float2 p01 = *(const float2*)(sX + rowA * XSTR + k + 8);
                float2 p11 = *(const float2*)(sX + rowB * XSTR + k + 8);
                split_pair(p00.x, p00.y, ah[kb][0], al[kb][0]);
                split_pair(p10.x, p10.y, ah[kb][1], al[kb][1]);
                split_pair(p01.x, p01.y, ah[kb][2], al[kb][2]);
                split_pair(p11.x, p11.y, ah[kb][3], al[kb][3]);
            }

            // scan ALL 512 codes
            float bestA = -3.4e38f, best2A = -3.4e38f;
            float bestB = -3.4e38f, best2B = -3.4e38f;
            int idxA = 0, idxB = 0;
            #pragma unroll 1
            for (int np = 0; np < 32; np++) {
                uint32_t base = sb + SM_BHI + (uint32_t)np * (16 * BSTR) + bofs;
                uint32_t bh[4][4], bl[4][4];
                #pragma unroll
                for (int kb = 0; kb < 4; kb++) ldsm_x4_nv(bh[kb], base + kb * 32);
                #pragma unroll
                for (int kb = 0; kb < 4; kb++) ldsm_x4_nv(bl[kb], base + kb * 32 + (SM_BLO - SM_BHI));
                #pragma unroll
                for (int h = 0; h < 2; h++) {
                    float c0 = 0.f, c1 = 0.f, c2 = 0.f, c3 = 0.f;
                    #pragma unroll
                    for (int kb = 0; kb < 4; kb++)
                        mma_bf16(c0,c1,c2,c3, ah[kb][0],ah[kb][1],ah[kb][2],ah[kb][3],
                                 bh[kb][2*h], bh[kb][2*h+1]);
                    #pragma unroll
                    for (int kb = 0; kb < 4; kb++)
                        mma_bf16(c0,c1,c2,c3, ah[kb][0],ah[kb][1],ah[kb][2],ah[kb][3],
                                 bl[kb][2*h], bl[kb][2*h+1]);
                    #pragma unroll
                    for (int kb = 0; kb < 4; kb++)
                        mma_bf16(c0,c1,c2,c3, al[kb][0],al[kb][1],al[kb][2],al[kb][3],
                                 bh[kb][2*h], bh[kb][2*h+1]);
                    int ncol = np * 16 + h * 8 + tig * 2;
                    float2 hn2 = *(const float2*)(shn + ncol);
                    float s0 = c0 - hn2.x, s1 = c1 - hn2.y;
                    float s2 = c2 - hn2.x, s3 = c3 - hn2.y;
                    UPD(bestA, best2A, idxA, s0, ncol);
                    UPD(bestA, best2A, idxA, s1, ncol + 1);
                    UPD(bestB, best2B, idxB, s2, ncol);
                    UPD(bestB, best2B, idxB, s3, ncol + 1);
                }
            }

            // in-register merge across tig (lanes differing in bits 0-1)
            #pragma unroll
            for (int m = 1; m <= 2; m <<= 1) {
                float ob  = __shfl_xor_sync(0xFFFFFFFFu, bestA, m);
                float ob2 = __shfl_xor_sync(0xFFFFFFFFu, best2A, m);
                int   oi  = __shfl_xor_sync(0xFFFFFFFFu, idxA, m);
                bool take = (ob > bestA) || (ob == bestA && oi < idxA);
                best2A = take ? fmaxf(bestA, ob2) : fmaxf(best2A, ob);
                bestA  = take ? ob : bestA;
                idxA   = take ? oi : idxA;
                ob  = __shfl_xor_sync(0xFFFFFFFFu, bestB, m);
                ob2 = __shfl_xor_sync(0xFFFFFFFFu, best2B, m);
                oi  = __shfl_xor_sync(0xFFFFFFFFu, idxB, m);
                take = (ob > bestB) || (ob == bestB && oi < idxB);
                best2B = take ? fmaxf(bestB, ob2) : fmaxf(best2B, ob);
                bestB  = take ? ob : bestB;
                idxB   = take ? oi : idxB;
            }

            // rare exact fp64 re-resolve (cooperative, within scan warp)
            for (int which = 0; which < 2; which++) {
                float bst = which ? bestB : bestA;
                float b2  = which ? best2B : best2A;
                unsigned need = __ballot_sync(0xFFFFFFFFu,
                                              (tig == 0) && (bst - b2 < TAU_GAP));
                while (need) {
                    const int src = __ffs(need) - 1;
                    need &= need - 1;
                    const int rowN = w * 16 + (src >> 2) + (which ? 8 : 0);
                    const float cut = __shfl_sync(0xFFFFFFFFu, bst, src) - TAU_BAND;
                    const float* xr = sX + rowN * XSTR;
                    double bd = 1e300; int bi = KK;
                    #pragma unroll 1
                    for (int kk = 0; kk < 16; kk++) {
                        const int k = lane * 16 + kk;
                        const float4* e4 = (const float4*)(emb + (size_t)k * DD);
                        float a0 = 0.f, a1 = 0.f, a2 = 0.f, a3 = 0.f;
                        #pragma unroll
                        for (int j = 0; j < 16; j++) {
                            float4 q = __ldg(e4 + j);
                            a0 = fmaf(xr[4*j+0], q.x, a0);
                            a1 = fmaf(xr[4*j+1], q.y, a1);
                            a2 = fmaf(xr[4*j+2], q.z, a2);
                            a3 = fmaf(xr[4*j+3], q.w, a3);
                        }
                        float s = (a0 + a1) + (a2 + a3) - shn[k];
                        if (s > cut) {
                            const float* e = emb + (size_t)k * DD;
                            double d0 = 0.0, d1 = 0.0;
                            #pragma unroll
                            for (int j = 0; j < 32; j++) {
                                double f0 = (double)xr[2*j]   - (double)__ldg(e + 2*j);
                                double f1 = (double)xr[2*j+1] - (double)__ldg(e + 2*j+1);
                                d0 = fma(f0, f0, d0);
                                d1 = fma(f1, f1, d1);
                            }
                            double dd = d0 + d1;
                            if (dd < bd || (dd == bd && k < bi)) { bd = dd; bi = k; }
                        }
                    }
                    #pragma unroll
                    for (int off = 16; off; off >>= 1) {
                        double obd = __shfl_xor_sync(0xFFFFFFFFu, bd, off);
                        int    obi = __shfl_xor_sync(0xFFFFFFFFu, bi, off);
                        if (obd < bd || (obd == bd && obi < bi)) { bd = obd; bi = obi; }
                    }
                    if (lane == src) { if (which) idxB = bi; else idxA = bi; }
                }
            }
            if (tig == 0) {
                int* bc = sBidx + (it & 1) * 128;
                bc[rowA] = idxA;
                bc[rowB] = idxB;
            }
        } else {
            // ================= AUX warps =================
            const int a = tid - 256;

            // ---- write out PREVIOUS tile ----
            if (it > 0) {
                const int ptile = tile - NCTA;
                const int pn0g = ptile << 7;
                const int pb = pn0g >> 12, phw = pn0g & 4095;
                const int* bp = sBidx + ((it - 1) & 1) * 128;
                const float* pX = sXb[p ^ 1];
                const int row = a & 127, hs = a >> 7;
                const int bidx = bp[row];
                const float* xr = pX + row * XSTR + hs * 32;
                const float4* eb = (const float4*)(emb + (size_t)bidx * DD + hs * 32);
                float* qo = out + QOUT_OFF + (size_t)pb * CCH * HWSZ + phw + row;
                float* qf = out + QFLAT_OFF + (size_t)(pn0g + row) * DD + hs * 32;
                float sse = 0.f;
                #pragma unroll
                for (int j = 0; j < 8; j++) {
                    float4 q = __ldg(eb + j);
                    const int d = hs * 32 + 4 * j;
                    float f0 = xr[4*j]   - q.x, f1 = xr[4*j+1] - q.y;
                    float f2 = xr[4*j+2] - q.z, f3 = xr[4*j+3] - q.w;
                    sse = fmaf(f0, f0, fmaf(f1, f1, fmaf(f2, f2, fmaf(f3, f3, sse))));
                    __stcs(qo + (size_t)d * HWSZ, q.x);
                    __stcs(qo + (size_t)(d+1) * HWSZ, q.y);
                    __stcs(qo + (size_t)(d+2) * HWSZ, q.z);
                    __stcs(qo + (size_t)(d+3) * HWSZ, q.w);
                    __stcs((float2*)(qf + 4*j),     make_float2(q.x, q.y));
                    __stcs((float2*)(qf + 4*j + 2), make_float2(q.z, q.w));
                }
                if (hs == 0) {
                    __stcs(out + ENC_OFF + (size_t)(pn0g + row) * KK + bidx, 1.0f);
                    atomicAdd(&shist[bidx], 1);
                }
                #pragma unroll
                for (int off = 16; off; off >>= 1)
                    sse += __shfl_xor_sync(0xFFFFFFFFu, sse, off);
                if (lane == 0) atomicAdd((double*)(smem + SM_SSE), (double)sse);
            }
            // aux-only barrier: prev-X reads done before prefetch overwrites
            asm volatile("bar.sync 2, 256;" ::: "memory");

            // ---- zero THIS tile's one-hot slab ----
            {
                float* ep = out + ENC_OFF + (size_t)n0g * KK;
                if (a == 0) *(float2*)ep = make_float2(0.f, 0.f);
                if (a == 1) *(float2*)(ep + 2 + 16383 * 4) = make_float2(0.f, 0.f);
                float4* e4z = (float4*)(ep + 2);
                const float4 z4 = make_float4(0.f, 0.f, 0.f, 0.f);
                for (int i = a; i < 16383; i += 256) __stcs(e4z + i, z4);
            }
            // ---- prefetch next tile's X ----
            const int nt = tile + NCTA;
            if (nt < NTILES) {
                const int nn = nt << 7;
                const float* nbase = in + (size_t)(nn >> 12) * CCH * HWSZ + (nn & 4095);
                const uint32_t sxn = sb + ((p ^ 1) ? SM_X1 : SM_X0);
                for (int i = a; i < 8192; i += 256) {
                    int d = i >> 7, r = i & 127;
                    cp_async4(sxn + (uint32_t)(r * XSTR + d) * 4,
                              nbase + (size_t)d * HWSZ + r);
                }
            }
            cp_wait_all();
        }
        __syncthreads();
    }

    // ---- final tile write-out (aux warps) ----
    {
        const int nit = (NTILES - cta + NCTA - 1) / NCTA;
        const int lt  = cta + (nit - 1) * NCTA;
        if (w >= 8) {
            const int a = tid - 256;
            const int pn0g = lt << 7;
            const int pb = pn0g >> 12, phw = pn0g & 4095;
            const int* bp = sBidx + ((nit - 1) & 1) * 128;
            const float* pX = sXb[(nit - 1) & 1];
            const int row = a & 127, hs = a >> 7;
            const int bidx = bp[row];
            const float* xr = pX + row * XSTR + hs * 32;
            const float4* eb = (const float4*)(emb + (size_t)bidx * DD + hs * 32);
            float* qo = out + QOUT_OFF + (size_t)pb * CCH * HWSZ + phw + row;
            float* qf = out + QFLAT_OFF + (size_t)(pn0g + row) * DD + hs * 32;
            float sse = 0.f;
            #pragma unroll
            for (int j = 0; j < 8; j++) {
                float4 q = __ldg(eb + j);
                const int d = hs * 32 + 4 * j;
                float f0 = xr[4*j]   - q.x, f1 = xr[4*j+1] - q.y;
                float f2 = xr[4*j+2] - q.z, f3 = xr[4*j+3] - q.w;
                sse = fmaf(f0, f0, fmaf(f1, f1, fmaf(f2, f2, fmaf(f3, f3, sse))));
                __stcs(qo + (size_t)d * HWSZ, q.x);
                __stcs(qo + (size_t)(d+1) * HWSZ, q.y);
                __stcs(qo + (size_t)(d+2) * HWSZ, q.z);
                __stcs(qo + (size_t)(d+3) * HWSZ, q.w);
                __stcs((float2*)(qf + 4*j),     make_float2(q.x, q.y));
                __stcs((float2*)(qf + 4*j + 2), make_float2(q.z, q.w));
            }
            if (hs == 0) {
                __stcs(out + ENC_OFF + (size_t)(pn0g + row) * KK + bidx, 1.0f);
                atomicAdd(&shist[bidx], 1);
            }
            #pragma unroll
            for (int off = 16; off; off >>= 1)
                sse += __shfl_xor_sync(0xFFFFFFFFu, sse, off);
            if (lane == 0) atomicAdd((double*)(smem + SM_SSE), (double)sse);
        }
    }
    __syncthreads();

    // ---- per-CTA flush ----
    for (int i = tid; i < KK; i += TPB) g_hist_part[cta][i] = shist[i];
    if (tid == 0) g_sse_part[cta] = *(double*)(smem + SM_SSE);
    __threadfence();
    __syncthreads();
    if (tid == 0) *(unsigned*)(smem + SM_FLAG) = atomicAdd(&g_done, 1u);
    __syncthreads();

    // ---- last CTA finalizes ----
    if (*(unsigned*)(smem + SM_FLAG) == NCTA - 1) {
        float* red = (float*)(smem + SM_HN);   // reuse (scan done)
        int s = 0;
        for (int c = 0; c < NCTA; c++) s += g_hist_part[c][tid];
        float pr = (float)s / (float)NFLAT;
        red[tid] = pr * logf(pr + 1e-10f);
        __syncthreads();
        #pragma unroll
        for (int st = 256; st; st >>= 1) {
            if (tid < st) red[tid] += red[tid + st];
            __syncthreads();
        }
        if (tid == 0) {
            double a = 0.0;
            for (int c = 0; c < NCTA; c++) a += g_sse_part[c];
            out[PERP_OFF] = expf(-red[0]);
            out[LOSS_OFF] = 0.25f * (float)(a / ((double)NFLAT * (double)DD));
            g_done = 0;
        }
    }
}

extern "C" void kernel_launch(void* const* d_in, const int* in_sizes, int n_in,
                              void* d_out, int out_size)
{
    const float* in  = (const float*)d_in[0];
    const float* emb = (const float*)d_in[1];
    float* out = (float*)d_out;

    cudaFuncSetAttribute(vq_mma_kernel,
                         cudaFuncAttributeMaxDynamicSharedMemorySize, SM_TOTAL);
    vq_mma_kernel<<<NCTA, TPB, SM_TOTAL>>>(in, emb, out);
}

// round 16
// speedup vs baseline: 1.2334x; 1.2334x over previous
#include <cuda_runtime.h>
#include <cuda_bf16.h>
#include <cstdint>

#define KK 512
#define DD 64
#define HWSZ 4096
#define CCH 64
#define NFLAT 131072
#define NTILES 1024            // NFLAT / 128
#define NCTA 148
#define TPB 512

#define LOSS_OFF   0ULL
#define QOUT_OFF   1ULL
#define PERP_OFF   8388609ULL
#define ENC_OFF    8388610ULL   // elem offset == 2 (mod 4)
#define QFLAT_OFF  75497474ULL  // elem offset == 2 (mod 4)

#define TAU_GAP  6e-4f
#define TAU_BAND 2.4e-3f

// ---- dynamic smem byte offsets ----
#define SM_HIST  0              // 512 int
#define SM_SSE   2048           // double
#define SM_FLAG  2056           // unsigned
#define SM_HN    2176           // 512 float
#define SM_BEST  4224           // 128 rows x 8 slots float
#define SM_BEST2 8320
#define SM_IDX   12416
#define SM_X0    16512          // 128 x 66 fp32 = 33792 B
#define SM_X1    50304
#define SM_BHI   84096          // 512 x 144B bf16
#define SM_BLO   157824
#define SM_XN    231552         // 128 float (||x||^2 per row)
#define SM_TOTAL 232064

#define XSTR 66
#define BSTR 144

__device__ int      g_hist_part[NCTA][KK];
__device__ double   g_sse_part[NCTA];
__device__ unsigned g_done;

__device__ __forceinline__ uint32_t smem_u32(const void* p) {
    uint32_t a;
    asm("{ .reg .u64 t; cvta.to.shared.u64 t, %1; cvt.u32.u64 %0, t; }" : "=r"(a) : "l"(p));
    return a;
}
// non-volatile: B tiles immutable after prologue
__device__ __forceinline__ void ldsm_x4_nv(uint32_t* r, uint32_t addr) {
    asm("ldmatrix.sync.aligned.m8n8.x4.shared.b16 {%0,%1,%2,%3}, [%4];"
        : "=r"(r[0]), "=r"(r[1]), "=r"(r[2]), "=r"(r[3]) : "r"(addr));
}
__device__ __forceinline__ void mma_bf16(float& c0, float& c1, float& c2, float& c3,
                                         uint32_t a0, uint32_t a1, uint32_t a2, uint32_t a3,
                                         uint32_t b0, uint32_t b1) {
    asm("mma.sync.aligned.m16n8k16.row.col.f32.bf16.bf16.f32 "
        "{%0,%1,%2,%3}, {%4,%5,%6,%7}, {%8,%9}, {%0,%1,%2,%3};"
        : "+f"(c0), "+f"(c1), "+f"(c2), "+f"(c3)
        : "r"(a0), "r"(a1), "r"(a2), "r"(a3), "r"(b0), "r"(b1));
}
__device__ __forceinline__ void cp_async4(uint32_t dst, const void* src) {
    asm volatile("cp.async.ca.shared.global [%0], [%1], 4;" :: "r"(dst), "l"(src));
}
__device__ __forceinline__ void cp_wait_all() {
    asm volatile("cp.async.wait_all;" ::: "memory");
}
__device__ __forceinline__ void split_pair(float f0, float f1, uint32_t& hi, uint32_t& lo) {
    __nv_bfloat16 h0 = __float2bfloat16_rn(f0), h1 = __float2bfloat16_rn(f1);
    hi = ((uint32_t)__bfloat16_as_ushort(h1) << 16) | (uint32_t)__bfloat16_as_ushort(h0);
    float r0 = f0 - __bfloat162float(h0), r1 = f1 - __bfloat162float(h1);
    __nv_bfloat16 l0 = __float2bfloat16_rn(r0), l1 = __float2bfloat16_rn(r1);
    lo = ((uint32_t)__bfloat16_as_ushort(l1) << 16) | (uint32_t)__bfloat16_as_ushort(l0);
}
#define UPD(b, b2, i, s, n) { bool p_ = (s) > (b); \
    (b2) = p_ ? (b) : fmaxf((b2), (s)); (i) = p_ ? (n) : (i); (b) = p_ ? (s) : (b); }

// ================= single fused kernel =================
__global__ __launch_bounds__(TPB, 1)
void vq_mma_kernel(const float* __restrict__ in,
                   const float* __restrict__ emb,
                   float* __restrict__ out)
{
    extern __shared__ __align__(128) char smem[];
    const uint32_t sb = smem_u32(smem);
    const int tid  = threadIdx.x;
    const int cta  = blockIdx.x;
    const int lane = tid & 31;
    const int w    = tid >> 5;
    const int half = w >> 3;
    const int grp  = lane >> 2;
    const int tig  = lane & 3;
    const int rowA = (w & 7) * 16 + grp;
    const int rowB = rowA + 8;

    const uint32_t bofs = (uint32_t)((lane & 7) + ((lane >> 4) & 1) * 8) * BSTR
                        + (uint32_t)((lane >> 3) & 1) * 16;

    int*    shist  = (int*)(smem + SM_HIST);
    float*  shn    = (float*)(smem + SM_HN);
    float*  sBest  = (float*)(smem + SM_BEST);
    float*  sBest2 = (float*)(smem + SM_BEST2);
    int*    sIdx   = (int*)(smem + SM_IDX);
    float*  sXn    = (float*)(smem + SM_XN);
    float*  sXb[2] = { (float*)(smem + SM_X0), (float*)(smem + SM_X1) };

    for (int i = tid; i < KK; i += TPB) shist[i] = 0;
    if (tid == 0) *(double*)(smem + SM_SSE) = 0.0;

    // ---- codebook -> SMEM bf16 hi/lo (once; immutable) ----
    for (int i = tid; i < KK * 16; i += TPB) {
        float4 v = __ldg((const float4*)emb + i);
        int r = i >> 4, c4 = i & 15;
        uint32_t h0, l0, h1, l1;
        split_pair(v.x, v.y, h0, l0);
        split_pair(v.z, v.w, h1, l1);
        *(uint2*)(smem + SM_BHI + r * BSTR + c4 * 8) = make_uint2(h0, h1);
        *(uint2*)(smem + SM_BLO + r * BSTR + c4 * 8) = make_uint2(l0, l1);
    }
    for (int r = tid; r < KK; r += TPB) {
        const float4* e4 = (const float4*)(emb + (size_t)r * DD);
        float acc = 0.f;
        #pragma unroll
        for (int j = 0; j < 16; j++) {
            float4 q = __ldg(e4 + j);
            acc = fmaf(q.x, q.x, acc); acc = fmaf(q.y, q.y, acc);
            acc = fmaf(q.z, q.z, acc); acc = fmaf(q.w, q.w, acc);
        }
        shn[r] = 0.5f * acc;
    }

    // ---- prologue: first X tile into buf 0 ----
    if (cta < NTILES) {
        const int n0g = cta << 7;
        const float* base = in + (size_t)(n0g >> 12) * CCH * HWSZ + (n0g & 4095);
        float* sX = sXb[0];
        for (int i = tid; i < 128 * DD; i += TPB) {
            int d = i >> 7, r = i & 127;
            sX[r * XSTR + d] = __ldg(base + (size_t)d * HWSZ + r);
        }
    }
    __syncthreads();

    int p = 0;
    for (int tile = cta; tile < NTILES; tile += NCTA, p ^= 1) {
        const int n0g = tile << 7;
        const int b   = n0g >> 12;
        const int hw0 = n0g & 4095;
        float* sX = sXb[p];

        const int  nt       = tile + NCTA;
        const bool nt_valid = (nt < NTILES);
        const float* nbase  = nt_valid
            ? in + (size_t)((nt << 7) >> 12) * CCH * HWSZ + ((nt << 7) & 4095) : nullptr;
        const uint32_t sxn  = sb + ((p ^ 1) ? SM_X1 : SM_X0);

        float*  ep  = out + ENC_OFF + (size_t)n0g * KK;
        float4* e4z = (float4*)(ep + 2);
        const float4 z4 = make_float4(0.f, 0.f, 0.f, 0.f);
        if (tid == 0)   *(float2*)ep = make_float2(0.f, 0.f);
        if (tid == 128) *(float2*)(ep + 2 + 16383 * 4) = make_float2(0.f, 0.f);

        // ---- build A fragments (hi/lo) from sX + per-row ||x||^2 partials ----
        uint32_t ah[4][4], al[4][4];
        float xnA = 0.f, xnB = 0.f;
        #pragma unroll
        for (int kb = 0; kb < 4; kb++) {
            int k = kb * 16 + tig * 2;
            float2 p00 = *(const float2*)(sX + rowA * XSTR + k);
            float2 p10 = *(const float2*)(sX + rowB * XSTR + k);
            float2 p01 = *(const float2*)(sX + rowA * XSTR + k + 8);
            float2 p11 = *(const float2*)(sX + rowB * XSTR + k + 8);
            split_pair(p00.x, p00.y, ah[kb][0], al[kb][0]);
            split_pair(p10.x, p10.y, ah[kb][1], al[kb][1]);
            split_pair(p01.x, p01.y, ah[kb][2], al[kb][2]);
            split_pair(p11.x, p11.y, ah[kb][3], al[kb][3]);
            xnA = fmaf(p00.x, p00.x, fmaf(p00.y, p00.y,
                  fmaf(p01.x, p01.x, fmaf(p01.y, p01.y, xnA))));
            xnB = fmaf(p10.x, p10.x, fmaf(p10.y, p10.y,
                  fmaf(p11.x, p11.x, fmaf(p11.y, p11.y, xnB))));
        }
        // sum over tig (lanes differing in bits 0-1)
        #pragma unroll
        for (int m = 1; m <= 2; m <<= 1) {
            xnA += __shfl_xor_sync(0xFFFFFFFFu, xnA, m);
            xnB += __shfl_xor_sync(0xFFFFFFFFu, xnB, m);
        }
        if (tig == 0 && half == 0) { sXn[rowA] = xnA; sXn[rowB] = xnB; }

        // ---- scan 256 codes + interleaved enc-zero + X prefetch ----
        float bestA = -3.4e38f, best2A = -3.4e38f;
        float bestB = -3.4e38f, best2B = -3.4e38f;
        int idxA = 0, idxB = 0;
        #pragma unroll 1
        for (int np = 0; np < 16; np++) {
            {
                int i = (np * TPB + tid) * 2;
                if (i < 16383)     __stcs(e4z + i, z4);
                if (i + 1 < 16383) __stcs(e4z + i + 1, z4);
            }
            if (nt_valid) {
                int j = np * TPB + tid;
                int d = j >> 7, r = j & 127;
                cp_async4(sxn + (uint32_t)(r * XSTR + d) * 4,
                          nbase + (size_t)d * HWSZ + r);
            }

            uint32_t base = sb + SM_BHI + (uint32_t)(half * 256 + np * 16) * BSTR + bofs;
            uint32_t bh[4][4], bl[4][4];
            #pragma unroll
            for (int kb = 0; kb < 4; kb++) ldsm_x4_nv(bh[kb], base + kb * 32);
            #pragma unroll
            for (int kb = 0; kb < 4; kb++) ldsm_x4_nv(bl[kb], base + kb * 32 + (SM_BLO - SM_BHI));
            #pragma unroll
            for (int h = 0; h < 2; h++) {
                float c0 = 0.f, c1 = 0.f, c2 = 0.f, c3 = 0.f;
                #pragma unroll
                for (int kb = 0; kb < 4; kb++)
                    mma_bf16(c0,c1,c2,c3, ah[kb][0],ah[kb][1],ah[kb][2],ah[kb][3],
                             bh[kb][2*h], bh[kb][2*h+1]);
                #pragma unroll
                for (int kb = 0; kb < 4; kb++)
                    mma_bf16(c0,c1,c2,c3, ah[kb][0],ah[kb][1],ah[kb][2],ah[kb][3],
                             bl[kb][2*h], bl[kb][2*h+1]);
                #pragma unroll
                for (int kb = 0; kb < 4; kb++)
                    mma_bf16(c0,c1,c2,c3, al[kb][0],al[kb][1],al[kb][2],al[kb][3],
                             bh[kb][2*h], bh[kb][2*h+1]);
                int ncol = half * 256 + np * 16 + h * 8 + tig * 2;
                float2 hn2 = *(const float2*)(shn + ncol);
                float s0 = c0 - hn2.x, s1 = c1 - hn2.y;
                float s2 = c2 - hn2.x, s3 = c3 - hn2.y;
                UPD(bestA, best2A, idxA, s0, ncol);
                UPD(bestA, best2A, idxA, s1, ncol + 1);
                UPD(bestB, best2B, idxB, s2, ncol);
                UPD(bestB, best2B, idxB, s3, ncol + 1);
            }
        }
        const int slot = half * 4 + tig;
        sBest [rowA * 8 + slot] = bestA;  sBest [rowB * 8 + slot] = bestB;
        sBest2[rowA * 8 + slot] = best2A; sBest2[rowB * 8 + slot] = best2B;
        sIdx  [rowA * 8 + slot] = idxA;   sIdx  [rowB * 8 + slot] = idxB;
        __syncthreads();

        // ---- combine + refine + write-out (no intermediate barrier) ----
        {
            const int  r      = tid >> 2;
            const bool active = (tid & 3) == 0;
            float best = -3.4e38f, b2 = -3.4e38f;
            int bidx = 0;
            #pragma unroll
            for (int t = 0; t < 8; t++) {
                float bb = sBest[r * 8 + t], bb2 = sBest2[r * 8 + t];
                int   ii = sIdx[r * 8 + t];
                if (bb > best) { b2 = fmaxf(best, bb2); best = bb; bidx = ii; }
                else           { b2 = fmaxf(b2, bb); }
            }
            // sse via score identity (exact fp64 value substituted if refined)
            float rsse = fmaf(-2.f, best, sXn[r]);

            unsigned needmask = __ballot_sync(0xFFFFFFFFu,
                                              active && (best - b2 < TAU_GAP));
            while (needmask) {
                const int src = __ffs(needmask) - 1;
                needmask &= needmask - 1;
                const int   rneed = __shfl_sync(0xFFFFFFFFu, r, src);
                const float cut   = __shfl_sync(0xFFFFFFFFu, best, src) - TAU_BAND;
                const float* xr = sX + rneed * XSTR;
                double bd = 1e300; int bi = KK;
                #pragma unroll 1
                for (int kk = 0; kk < 16; kk++) {
                    const int k = lane * 16 + kk;
                    const float4* e4 = (const float4*)(emb + (size_t)k * DD);
                    float a0 = 0.f, a1 = 0.f, a2 = 0.f, a3 = 0.f;
                    #pragma unroll
                    for (int j = 0; j < 16; j++) {
                        float4 q = __ldg(e4 + j);
                        a0 = fmaf(xr[4*j+0], q.x, a0);
                        a1 = fmaf(xr[4*j+1], q.y, a1);
                        a2 = fmaf(xr[4*j+2], q.z, a2);
                        a3 = fmaf(xr[4*j+3], q.w, a3);
                    }
                    float s = (a0 + a1) + (a2 + a3) - shn[k];
                    if (s > cut) {
                        const float* e = emb + (size_t)k * DD;
                        double d0 = 0.0, d1 = 0.0;
                        #pragma unroll
                        for (int j = 0; j < 32; j++) {
                            double f0 = (double)xr[2*j]   - (double)__ldg(e + 2*j);
                            double f1 = (double)xr[2*j+1] - (double)__ldg(e + 2*j+1);
                            d0 = fma(f0, f0, d0);
                            d1 = fma(f1, f1, d1);
                        }
                        double dd = d0 + d1;
                        if (dd < bd || (dd == bd && k < bi)) { bd = dd; bi = k; }
                    }
                }
                #pragma unroll
                for (int off = 16; off; off >>= 1) {
                    double obd = __shfl_xor_sync(0xFFFFFFFFu, bd, off);
                    int    obi = __shfl_xor_sync(0xFFFFFFFFu, bi, off);
                    if (obd < bd || (obd == bd && obi < bi)) { bd = obd; bi = obi; }
                }
                if (lane == src) { bidx = bi; rsse = (float)bd; }
            }

            // sse reduction: one value per row, held by active lanes
            float v = active ? rsse : 0.f;
            #pragma unroll
            for (int off = 16; off; off >>= 1) v += __shfl_xor_sync(0xFFFFFFFFu, v, off);
            if (lane == 0) atomicAdd((double*)(smem + SM_SSE), (double)v);

            // broadcast bidx from group leader (same warp) — no barrier needed
            const int bx = __shfl_sync(0xFFFFFFFFu, bidx, lane & ~3);

            // ---- write-out: 4 threads per row, 16 dims each ----
            const int sub = tid & 3;
            float e[16];
            const float4* ep4 = (const float4*)(emb + (size_t)bx * DD + sub * 16);
            #pragma unroll
            for (int j = 0; j < 4; j++) {
                float4 q = __ldg(ep4 + j);
                e[4*j] = q.x; e[4*j+1] = q.y; e[4*j+2] = q.z; e[4*j+3] = q.w;
            }

            float* qo = out + QOUT_OFF + (size_t)b * CCH * HWSZ + hw0 + r
                        + (size_t)(sub * 16) * HWSZ;
            #pragma unroll
            for (int c = 0; c < 16; c++) __stcs(qo + (size_t)c * HWSZ, e[c]);

            float* qf = out + QFLAT_OFF + (size_t)(n0g + r) * DD + sub * 16; // ≡2 mod 4
            #pragma unroll
            for (int j = 0; j < 8; j++)
                __stcs((float2*)(qf + 2*j), make_float2(e[2*j], e[2*j+1]));

            if (sub == 0) {
                __stcs(ep + (size_t)r * KK + bx, 1.0f);
                atomicAdd(&shist[bx], 1);
            }
        }

        cp_wait_all();
        __syncthreads();
    }

    // ---- per-CTA flush ----
    for (int i = tid; i < KK; i += TPB) g_hist_part[cta][i] = shist[i];
    if (tid == 0) g_sse_part[cta] = *(double*)(smem + SM_SSE);
    __threadfence();
    __syncthreads();
    if (tid == 0) *(unsigned*)(smem + SM_FLAG) = atomicAdd(&g_done, 1u);
    __syncthreads();

    // ---- last CTA finalizes ----
    if (*(unsigned*)(smem + SM_FLAG) == NCTA - 1) {
        float* red = (float*)(smem + SM_BEST);
        int s = 0;
        for (int c = 0; c < NCTA; c++) s += g_hist_part[c][tid];
        float pr = (float)s / (float)NFLAT;
        red[tid] = pr * logf(pr + 1e-10f);
        __syncthreads();
        #pragma unroll
        for (int st = 256; st; st >>= 1) {
            if (tid < st) red[tid] += red[tid + st];
            __syncthreads();
        }
        if (tid == 0) {
            double a = 0.0;
            for (int c = 0; c < NCTA; c++) a += g_sse_part[c];
            out[PERP_OFF] = expf(-red[0]);
            out[LOSS_OFF] = 0.25f * (float)(a / ((double)NFLAT * (double)DD));
            g_done = 0;
        }
    }
}

extern "C" void kernel_launch(void* const* d_in, const int* in_sizes, int n_in,
                              void* d_out, int out_size)
{
    const float* in  = (const float*)d_in[0];
    const float* emb = (const float*)d_in[1];
    float* out = (float*)d_out;

    cudaFuncSetAttribute(vq_mma_kernel,
                         cudaFuncAttributeMaxDynamicSharedMemorySize, SM_TOTAL);
    vq_mma_kernel<<<NCTA, TPB, SM_TOTAL>>>(in, emb, out);
}

// round 17
// speedup vs baseline: 1.2614x; 1.0227x over previous
#include <cuda_runtime.h>
#include <cuda_bf16.h>
#include <cstdint>

#define KK 512
#define DD 64
#define HWSZ 4096
#define CCH 64
#define NFLAT 131072
#define NTILES 1024            // NFLAT / 128
#define NCTA 148
#define TPB 512

#define LOSS_OFF   0ULL
#define QOUT_OFF   1ULL
#define PERP_OFF   8388609ULL
#define ENC_OFF    8388610ULL   // elem offset == 2 (mod 4)
#define QFLAT_OFF  75497474ULL  // elem offset == 2 (mod 4)

#define TAU_GAP  6e-4f
#define TAU_BAND 2.4e-3f

// ---- dynamic smem byte offsets ----
#define SM_HIST  0              // 512 int
#define SM_SSE   2048           // double
#define SM_FLAG  2056           // unsigned
#define SM_HN    2176           // 512 float
#define SM_BEST  4224           // 128 rows x 2 halves float
#define SM_BEST2 5248
#define SM_IDX   6272
#define SM_XN    7296           // 128 float (||x||^2 per row)
#define SM_X0    7936           // 128 x 66 fp32 = 33792 B
#define SM_X1    41728
#define SM_BHI   75520          // 512 x 144B bf16
#define SM_BLO   149248
#define SM_TOTAL 222976

#define XSTR 66
#define BSTR 144

__device__ int      g_hist_part[NCTA][KK];
__device__ double   g_sse_part[NCTA];
__device__ unsigned g_done;

__device__ __forceinline__ uint32_t smem_u32(const void* p) {
    uint32_t a;
    asm("{ .reg .u64 t; cvta.to.shared.u64 t, %1; cvt.u32.u64 %0, t; }" : "=r"(a) : "l"(p));
    return a;
}
// non-volatile: B tiles immutable after prologue
__device__ __forceinline__ void ldsm_x4_nv(uint32_t* r, uint32_t addr) {
    asm("ldmatrix.sync.aligned.m8n8.x4.shared.b16 {%0,%1,%2,%3}, [%4];"
        : "=r"(r[0]), "=r"(r[1]), "=r"(r[2]), "=r"(r[3]) : "r"(addr));
}
__device__ __forceinline__ void mma_bf16(float& c0, float& c1, float& c2, float& c3,
                                         uint32_t a0, uint32_t a1, uint32_t a2, uint32_t a3,
                                         uint32_t b0, uint32_t b1) {
    asm("mma.sync.aligned.m16n8k16.row.col.f32.bf16.bf16.f32 "
        "{%0,%1,%2,%3}, {%4,%5,%6,%7}, {%8,%9}, {%0,%1,%2,%3};"
        : "+f"(c0), "+f"(c1), "+f"(c2), "+f"(c3)
        : "r"(a0), "r"(a1), "r"(a2), "r"(a3), "r"(b0), "r"(b1));
}
__device__ __forceinline__ void cp_async4(uint32_t dst, const void* src) {
    asm volatile("cp.async.ca.shared.global [%0], [%1], 4;" :: "r"(dst), "l"(src));
}
__device__ __forceinline__ void cp_wait_all() {
    asm volatile("cp.async.wait_all;" ::: "memory");
}
__device__ __forceinline__ void split_pair(float f0, float f1, uint32_t& hi, uint32_t& lo) {
    __nv_bfloat16 h0 = __float2bfloat16_rn(f0), h1 = __float2bfloat16_rn(f1);
    hi = ((uint32_t)__bfloat16_as_ushort(h1) << 16) | (uint32_t)__bfloat16_as_ushort(h0);
    float r0 = f0 - __bfloat162float(h0), r1 = f1 - __bfloat162float(h1);
    __nv_bfloat16 l0 = __float2bfloat16_rn(r0), l1 = __float2bfloat16_rn(r1);
    lo = ((uint32_t)__bfloat16_as_ushort(l1) << 16) | (uint32_t)__bfloat16_as_ushort(l0);
}
#define UPD(b, b2, i, s, n) { bool p_ = (s) > (b); \
    (b2) = p_ ? (b) : fmaxf((b2), (s)); (i) = p_ ? (n) : (i); (b) = p_ ? (s) : (b); }

// ================= single fused kernel =================
__global__ __launch_bounds__(TPB, 1)
void vq_mma_kernel(const float* __restrict__ in,
                   const float* __restrict__ emb,
                   float* __restrict__ out)
{
    extern __shared__ __align__(128) char smem[];
    const uint32_t sb = smem_u32(smem);
    const int tid  = threadIdx.x;
    const int cta  = blockIdx.x;
    const int lane = tid & 31;
    const int w    = tid >> 5;
    const int half = w >> 3;
    const int wb   = w & 7;              // row-group id (warp pair id)
    const int grp  = lane >> 2;
    const int tig  = lane & 3;
    const int rowA = wb * 16 + grp;
    const int rowB = rowA + 8;

    const uint32_t bofs = (uint32_t)((lane & 7) + ((lane >> 4) & 1) * 8) * BSTR
                        + (uint32_t)((lane >> 3) & 1) * 16;

    int*    shist  = (int*)(smem + SM_HIST);
    float*  shn    = (float*)(smem + SM_HN);
    float*  sB1    = (float*)(smem + SM_BEST);   // [row*2 + half]
    float*  sB2    = (float*)(smem + SM_BEST2);
    int*    sIx    = (int*)(smem + SM_IDX);
    float*  sXn    = (float*)(smem + SM_XN);
    float*  sXb[2] = { (float*)(smem + SM_X0), (float*)(smem + SM_X1) };

    for (int i = tid; i < KK; i += TPB) shist[i] = 0;
    if (tid == 0) *(double*)(smem + SM_SSE) = 0.0;

    // ---- codebook -> SMEM bf16 hi/lo (once; immutable) ----
    for (int i = tid; i < KK * 16; i += TPB) {
        float4 v = __ldg((const float4*)emb + i);
        int r = i >> 4, c4 = i & 15;
        uint32_t h0, l0, h1, l1;
        split_pair(v.x, v.y, h0, l0);
        split_pair(v.z, v.w, h1, l1);
        *(uint2*)(smem + SM_BHI + r * BSTR + c4 * 8) = make_uint2(h0, h1);
        *(uint2*)(smem + SM_BLO + r * BSTR + c4 * 8) = make_uint2(l0, l1);
    }
    for (int r = tid; r < KK; r += TPB) {
        const float4* e4 = (const float4*)(emb + (size_t)r * DD);
        float acc = 0.f;
        #pragma unroll
        for (int j = 0; j < 16; j++) {
            float4 q = __ldg(e4 + j);
            acc = fmaf(q.x, q.x, acc); acc = fmaf(q.y, q.y, acc);
            acc = fmaf(q.z, q.z, acc); acc = fmaf(q.w, q.w, acc);
        }
        shn[r] = 0.5f * acc;
    }

    // ---- prologue: first X tile into buf 0 ----
    if (cta < NTILES) {
        const int n0g = cta << 7;
        const float* base = in + (size_t)(n0g >> 12) * CCH * HWSZ + (n0g & 4095);
        float* sX = sXb[0];
        for (int i = tid; i < 128 * DD; i += TPB) {
            int d = i >> 7, r = i & 127;
            sX[r * XSTR + d] = __ldg(base + (size_t)d * HWSZ + r);
        }
    }
    __syncthreads();

    int p = 0;
    for (int tile = cta; tile < NTILES; tile += NCTA, p ^= 1) {
        const int n0g = tile << 7;
        const int b   = n0g >> 12;
        const int hw0 = n0g & 4095;
        float* sX = sXb[p];

        const int  nt       = tile + NCTA;
        const bool nt_valid = (nt < NTILES);
        const float* nbase  = nt_valid
            ? in + (size_t)((nt << 7) >> 12) * CCH * HWSZ + ((nt << 7) & 4095) : nullptr;
        const uint32_t sxn  = sb + ((p ^ 1) ? SM_X1 : SM_X0);

        float*  ep  = out + ENC_OFF + (size_t)n0g * KK;
        float4* e4z = (float4*)(ep + 2);
        const float4 z4 = make_float4(0.f, 0.f, 0.f, 0.f);
        if (tid == 0)   *(float2*)ep = make_float2(0.f, 0.f);
        if (tid == 128) *(float2*)(ep + 2 + 16383 * 4) = make_float2(0.f, 0.f);

        // ---- build A fragments (hi/lo) from sX + per-row ||x||^2 partials ----
        uint32_t ah[4][4], al[4][4];
        float xnA = 0.f, xnB = 0.f;
        #pragma unroll
        for (int kb = 0; kb < 4; kb++) {
            int k = kb * 16 + tig * 2;
            float2 p00 = *(const float2*)(sX + rowA * XSTR + k);
            float2 p10 = *(const float2*)(sX + rowB * XSTR + k);
            float2 p01 = *(const float2*)(sX + rowA * XSTR + k + 8);
            float2 p11 = *(const float2*)(sX + rowB * XSTR + k + 8);
            split_pair(p00.x, p00.y, ah[kb][0], al[kb][0]);
            split_pair(p10.x, p10.y, ah[kb][1], al[kb][1]);
            split_pair(p01.x, p01.y, ah[kb][2], al[kb][2]);
            split_pair(p11.x, p11.y, ah[kb][3], al[kb][3]);
            xnA = fmaf(p00.x, p00.x, fmaf(p00.y, p00.y,
                  fmaf(p01.x, p01.x, fmaf(p01.y, p01.y, xnA))));
            xnB = fmaf(p10.x, p10.x, fmaf(p10.y, p10.y,
                  fmaf(p11.x, p11.x, fmaf(p11.y, p11.y, xnB))));
        }
        #pragma unroll
        for (int m = 1; m <= 2; m <<= 1) {
            xnA += __shfl_xor_sync(0xFFFFFFFFu, xnA, m);
            xnB += __shfl_xor_sync(0xFFFFFFFFu, xnB, m);
        }
        if (tig == 0 && half == 0) { sXn[rowA] = xnA; sXn[rowB] = xnB; }

        // ---- scan 256 codes + interleaved enc-zero + X prefetch ----
        float bestA = -3.4e38f, best2A = -3.4e38f;
        float bestB = -3.4e38f, best2B = -3.4e38f;
        int idxA = 0, idxB = 0;
        #pragma unroll 1
        for (int np = 0; np < 16; np++) {
            {
                int i = (np * TPB + tid) * 2;
                if (i < 16383)     __stcs(e4z + i, z4);
                if (i + 1 < 16383) __stcs(e4z + i + 1, z4);
            }
            if (nt_valid) {
                int j = np * TPB + tid;
                int d = j >> 7, r = j & 127;
                cp_async4(sxn + (uint32_t)(r * XSTR + d) * 4,
                          nbase + (size_t)d * HWSZ + r);
            }

            uint32_t base = sb + SM_BHI + (uint32_t)(half * 256 + np * 16) * BSTR + bofs;
            uint32_t bh[4][4], bl[4][4];
            #pragma unroll
            for (int kb = 0; kb < 4; kb++) ldsm_x4_nv(bh[kb], base + kb * 32);
            #pragma unroll
            for (int kb = 0; kb < 4; kb++) ldsm_x4_nv(bl[kb], base + kb * 32 + (SM_BLO - SM_BHI));
            #pragma unroll
            for (int h = 0; h < 2; h++) {
                float c0 = 0.f, c1 = 0.f, c2 = 0.f, c3 = 0.f;
                #pragma unroll
                for (int kb = 0; kb < 4; kb++)
                    mma_bf16(c0,c1,c2,c3, ah[kb][0],ah[kb][1],ah[kb][2],ah[kb][3],
                             bh[kb][2*h], bh[kb][2*h+1]);
                #pragma unroll
                for (int kb = 0; kb < 4; kb++)
                    mma_bf16(c0,c1,c2,c3, ah[kb][0],ah[kb][1],ah[kb][2],ah[kb][3],
                             bl[kb][2*h], bl[kb][2*h+1]);
                #pragma unroll
                for (int kb = 0; kb < 4; kb++)
                    mma_bf16(c0,c1,c2,c3, al[kb][0],al[kb][1],al[kb][2],al[kb][3],
                             bh[kb][2*h], bh[kb][2*h+1]);
                int ncol = half * 256 + np * 16 + h * 8 + tig * 2;
                float2 hn2 = *(const float2*)(shn + ncol);
                float s0 = c0 - hn2.x, s1 = c1 - hn2.y;
                float s2 = c2 - hn2.x, s3 = c3 - hn2.y;
                UPD(bestA, best2A, idxA, s0, ncol);
                UPD(bestA, best2A, idxA, s1, ncol + 1);
                UPD(bestB, best2B, idxB, s2, ncol);
                UPD(bestB, best2B, idxB, s3, ncol + 1);
            }
        }

        // ---- in-register tig merge (lanes differing in bits 0-1) ----
        #pragma unroll
        for (int m = 1; m <= 2; m <<= 1) {
            float ob  = __shfl_xor_sync(0xFFFFFFFFu, bestA, m);
            float ob2 = __shfl_xor_sync(0xFFFFFFFFu, best2A, m);
            int   oi  = __shfl_xor_sync(0xFFFFFFFFu, idxA, m);
            bool take = (ob > bestA) || (ob == bestA && oi < idxA);
            best2A = take ? fmaxf(bestA, ob2) : fmaxf(best2A, ob);
            bestA  = take ? ob : bestA;
            idxA   = take ? oi : idxA;
            ob  = __shfl_xor_sync(0xFFFFFFFFu, bestB, m);
            ob2 = __shfl_xor_sync(0xFFFFFFFFu, best2B, m);
            oi  = __shfl_xor_sync(0xFFFFFFFFu, idxB, m);
            take = (ob > bestB) || (ob == bestB && oi < idxB);
            best2B = take ? fmaxf(bestB, ob2) : fmaxf(best2B, ob);
            bestB  = take ? ob : bestB;
            idxB   = take ? oi : idxB;
        }
        if (tig == 0) {
            sB1[rowA * 2 + half] = bestA;  sB1[rowB * 2 + half] = bestB;
            sB2[rowA * 2 + half] = best2A; sB2[rowB * 2 + half] = best2B;
            sIx[rowA * 2 + half] = idxA;   sIx[rowB * 2 + half] = idxB;
        }

        // ---- warp-pair sync (64 threads): decoupled from other pairs ----
        asm volatile("bar.sync %0, 64;" :: "r"(wb + 1) : "memory");

        // ---- combine + refine + write-out: this warp owns 8 rows ----
        {
            const int r   = wb * 16 + half * 8 + (lane >> 2);
            const int sub = lane & 3;

            float b0 = sB1[r * 2],     b1 = sB1[r * 2 + 1];
            float q0 = sB2[r * 2],     q1 = sB2[r * 2 + 1];
            int   i0 = sIx[r * 2],     i1 = sIx[r * 2 + 1];
            bool take = (b1 > b0);     // tie keeps half0 (smaller idx)
            float best  = take ? b1 : b0;
            int   bidx  = take ? i1 : i0;
            float b2    = take ? fmaxf(b0, q1) : fmaxf(b1, q0);
            float rsse  = fmaf(-2.f, best, sXn[r]);

            unsigned needmask = __ballot_sync(0xFFFFFFFFu,
                                              (sub == 0) && (best - b2 < TAU_GAP));
            while (needmask) {
                const int src = __ffs(needmask) - 1;
                needmask &= needmask - 1;
                const int   rneed = __shfl_sync(0xFFFFFFFFu, r, src);
                const float cut   = __shfl_sync(0xFFFFFFFFu, best, src) - TAU_BAND;
                const float* xr = sX + rneed * XSTR;
                double bd = 1e300; int bi = KK;
                #pragma unroll 1
                for (int kk = 0; kk < 16; kk++) {
                    const int k = lane * 16 + kk;
                    const float4* e4 = (const float4*)(emb + (size_t)k * DD);
                    float a0 = 0.f, a1 = 0.f, a2 = 0.f, a3 = 0.f;
                    #pragma unroll
                    for (int j = 0; j < 16; j++) {
                        float4 q = __ldg(e4 + j);
                        a0 = fmaf(xr[4*j+0], q.x, a0);
                        a1 = fmaf(xr[4*j+1], q.y, a1);
                        a2 = fmaf(xr[4*j+2], q.z, a2);
                        a3 = fmaf(xr[4*j+3], q.w, a3);
                    }
                    float s = (a0 + a1) + (a2 + a3) - shn[k];
                    if (s > cut) {
                        const float* e = emb + (size_t)k * DD;
                        double d0 = 0.0, d1 = 0.0;
                        #pragma unroll
                        for (int j = 0; j < 32; j++) {
                            double f0 = (double)xr[2*j]   - (double)__ldg(e + 2*j);
                            double f1 = (double)xr[2*j+1] - (double)__ldg(e + 2*j+1);
                            d0 = fma(f0, f0, d0);
                            d1 = fma(f1, f1, d1);
                        }
                        double dd = d0 + d1;
                        if (dd < bd || (dd == bd && k < bi)) { bd = dd; bi = k; }
                    }
                }
                #pragma unroll
                for (int off = 16; off; off >>= 1) {
                    double obd = __shfl_xor_sync(0xFFFFFFFFu, bd, off);
                    int    obi = __shfl_xor_sync(0xFFFFFFFFu, bi, off);
                    if (obd < bd || (obd == bd && obi < bi)) { bd = obd; bi = obi; }
                }
                if (lane == src) { bidx = bi; rsse = (float)bd; }
            }

            // sse reduction: sub==0 lanes carry the row value
            float v = (sub == 0) ? rsse : 0.f;
            #pragma unroll
            for (int off = 16; off; off >>= 1) v += __shfl_xor_sync(0xFFFFFFFFu, v, off);
            if (lane == 0) atomicAdd((double*)(smem + SM_SSE), (double)v);

            // broadcast refined bidx from the row's sub==0 lane
            const int bx = __shfl_sync(0xFFFFFFFFu, bidx, lane & ~3);

            // write-out: 4 threads per row, 16 dims each
            float e[16];
            const float4* ep4 = (const float4*)(emb + (size_t)bx * DD + sub * 16);
            #pragma unroll
            for (int j = 0; j < 4; j++) {
                float4 q = __ldg(ep4 + j);
                e[4*j] = q.x; e[4*j+1] = q.y; e[4*j+2] = q.z; e[4*j+3] = q.w;
            }

            float* qo = out + QOUT_OFF + (size_t)b * CCH * HWSZ + hw0 + r
                        + (size_t)(sub * 16) * HWSZ;
            #pragma unroll
            for (int c = 0; c < 16; c++) __stcs(qo + (size_t)c * HWSZ, e[c]);

            float* qf = out + QFLAT_OFF + (size_t)(n0g + r) * DD + sub * 16; // ≡2 mod 4
            #pragma unroll
            for (int j = 0; j < 8; j++)
                __stcs((float2*)(qf + 2*j), make_float2(e[2*j], e[2*j+1]));

            if (sub == 0) {
                __stcs(ep + (size_t)r * KK + bx, 1.0f);
                atomicAdd(&shist[bx], 1);
            }
        }

        cp_wait_all();
        __syncthreads();
    }

    // ---- per-CTA flush ----
    for (int i = tid; i < KK; i += TPB) g_hist_part[cta][i] = shist[i];
    if (tid == 0) g_sse_part[cta] = *(double*)(smem + SM_SSE);
    __threadfence();
    __syncthreads();
    if (tid == 0) *(unsigned*)(smem + SM_FLAG) = atomicAdd(&g_done, 1u);
    __syncthreads();

    // ---- last CTA finalizes ----
    if (*(unsigned*)(smem + SM_FLAG) == NCTA - 1) {
        float* red = (float*)(smem + SM_X0);   // reuse (scan done)
        int s = 0;
        for (int c = 0; c < NCTA; c++) s += g_hist_part[c][tid];
        float pr = (float)s / (float)NFLAT;
        red[tid] = pr * logf(pr + 1e-10f);
        __syncthreads();
        #pragma unroll
        for (int st = 256; st; st >>= 1) {
            if (tid < st) red[tid] += red[tid + st];
            __syncthreads();
        }
        if (tid == 0) {
            double a = 0.0;
            for (int c = 0; c < NCTA; c++) a += g_sse_part[c];
            out[PERP_OFF] = expf(-red[0]);
            out[LOSS_OFF] = 0.25f * (float)(a / ((double)NFLAT * (double)DD));
            g_done = 0;
        }
    }
}

extern "C" void kernel_launch(void* const* d_in, const int* in_sizes, int n_in,
                              void* d_out, int out_size)
{
    const float* in  = (const float*)d_in[0];
    const float* emb = (const float*)d_in[1];
    float* out = (float*)d_out;

    cudaFuncSetAttribute(vq_mma_kernel,
                         cudaFuncAttributeMaxDynamicSharedMemorySize, SM_TOTAL);
    vq_mma_kernel<<<NCTA, TPB, SM_TOTAL>>>(in, emb, out);
}